// round 3
// baseline (speedup 1.0000x reference)
#include <cuda_runtime.h>
#include <cstddef>

// GloVe loss — locality-optimized via counting-sort bucketing by center index.
// Pipeline (one CUDA graph, 4 launches):
//   1) hist:    bucket histogram of center>>7
//   2) scan:    exclusive scan of counts -> cursors  (also re-zeros counts for next replay)
//   3) scatter: write {c, o, cooc, weight} records grouped by bucket
//   4) main:    walk records in bucket order -> center gathers are L2-local,
//               outside table gets (almost) the whole L2.

static constexpr int EMB           = 300;
static constexpr int NV4           = EMB / 4;       // 75 float4 per row
static constexpr int BATCH_N       = 262144;
static constexpr int THREADS       = 256;
static constexpr int WARPS_PER_BLK = THREADS / 32;  // 8
static constexpr int ROWS_PER_WARP = 4;
static constexpr int BLOCKS        = BATCH_N / (WARPS_PER_BLK * ROWS_PER_WARP); // 8192

static constexpr int BUCKET_SHIFT  = 7;
static constexpr int NBUCKETS      = 1024;          // covers 100000>>7 = 782 buckets

// Replay-safe device state. Zero-initialized at module load; each launch
// restores everything it dirties (scan re-zeros s_cnt, main resets g_acc/g_done).
__device__ int    s_cnt[NBUCKETS];
__device__ int    s_alloc[NBUCKETS];
__device__ int4   s_recs[BATCH_N];                  // {c, o, cooc_bits, weight_bits}
__device__ double g_acc;
__device__ unsigned int g_done;

// ---- 1) histogram -----------------------------------------------------------
__global__ __launch_bounds__(THREADS) void glove_hist_kernel(
    const int* __restrict__ center)
{
    const int i = blockIdx.x * THREADS + threadIdx.x;
    const int c = __ldg(center + i);
    atomicAdd(&s_cnt[c >> BUCKET_SHIFT], 1);
}

// ---- 2) exclusive scan (single block, 1024 threads) -------------------------
__global__ __launch_bounds__(NBUCKETS) void glove_scan_kernel()
{
    __shared__ int tmp[NBUCKETS];
    const int t = threadIdx.x;
    const int v = s_cnt[t];
    tmp[t] = v;
    __syncthreads();
    #pragma unroll
    for (int off = 1; off < NBUCKETS; off <<= 1) {
        int u = (t >= off) ? tmp[t - off] : 0;
        __syncthreads();
        tmp[t] += u;
        __syncthreads();
    }
    s_alloc[t] = tmp[t] - v;   // exclusive prefix = bucket start cursor
    s_cnt[t]   = 0;            // restore for next replay (deterministic state)
}

// ---- 3) scatter into bucket-grouped records ---------------------------------
__global__ __launch_bounds__(THREADS) void glove_scatter_kernel(
    const int*   __restrict__ center,
    const int*   __restrict__ outside,
    const float* __restrict__ coocs,
    const float* __restrict__ weighting)
{
    const int i = blockIdx.x * THREADS + threadIdx.x;
    const int c = __ldg(center + i);
    int4 rec;
    rec.x = c;
    rec.y = __ldg(outside + i);
    rec.z = __float_as_int(__ldg(coocs + i));
    rec.w = __float_as_int(__ldg(weighting + i));
    const int pos = atomicAdd(&s_alloc[c >> BUCKET_SHIFT], 1);
    s_recs[pos] = rec;
}

// ---- 4) main gather + reduce ------------------------------------------------
__global__ __launch_bounds__(THREADS) void glove_main_kernel(
    const float* __restrict__ cemb,
    const float* __restrict__ oemb,
    const float* __restrict__ cbias,
    const float* __restrict__ obias,
    float*       __restrict__ out)
{
    const int lane  = threadIdx.x & 31;
    const int warp  = threadIdx.x >> 5;
    const int gwarp = blockIdx.x * WARPS_PER_BLK + warp;

    float wsum = 0.0f;

    #pragma unroll
    for (int r = 0; r < ROWS_PER_WARP; ++r) {
        const int row = gwarp * ROWS_PER_WARP + r;
        const int4 rec = s_recs[row];
        const int ci = rec.x;
        const int oi = rec.y;

        const float4* __restrict__ ca = reinterpret_cast<const float4*>(cemb + (size_t)ci * EMB);
        const float4* __restrict__ ob = reinterpret_cast<const float4*>(oemb + (size_t)oi * EMB);

        // 6 independent LDG.E.128 front-batched (R1 proven structure).
        float4 a0 = __ldg(ca + lane);
        float4 b0 = __ldg(ob + lane);
        float4 a1 = __ldg(ca + lane + 32);
        float4 b1 = __ldg(ob + lane + 32);
        float4 a2 = make_float4(0.f, 0.f, 0.f, 0.f);
        float4 b2 = make_float4(0.f, 0.f, 0.f, 0.f);
        if (lane < NV4 - 64) {   // lanes 0..10 cover float4 indices 64..74
            a2 = __ldg(ca + lane + 64);
            b2 = __ldg(ob + lane + 64);
        }

        float dot = a0.x * b0.x + a0.y * b0.y + a0.z * b0.z + a0.w * b0.w;
        dot      += a1.x * b1.x + a1.y * b1.y + a1.z * b1.z + a1.w * b1.w;
        dot      += a2.x * b2.x + a2.y * b2.y + a2.z * b2.z + a2.w * b2.w;

        #pragma unroll
        for (int off = 16; off; off >>= 1)
            dot += __shfl_xor_sync(0xffffffffu, dot, off);

        if (lane == 0) {
            const float err = dot + __ldg(cbias + ci) + __ldg(obias + oi)
                            - __int_as_float(rec.z);
            wsum += __int_as_float(rec.w) * err * err;
        }
    }

    __shared__ float sh[WARPS_PER_BLK];
    if (lane == 0) sh[warp] = wsum;
    __syncthreads();

    if (threadIdx.x == 0) {
        float s = 0.0f;
        #pragma unroll
        for (int i = 0; i < WARPS_PER_BLK; ++i) s += sh[i];
        atomicAdd(&g_acc, (double)s);

        __threadfence();
        const unsigned t = atomicAdd(&g_done, 1u);
        if (t == (unsigned)(BLOCKS - 1)) {
            const double v = atomicAdd(&g_acc, 0.0);
            out[0] = (float)v;
            g_acc  = 0.0;
            g_done = 0u;
        }
    }
}

extern "C" void kernel_launch(void* const* d_in, const int* in_sizes, int n_in,
                              void* d_out, int out_size) {
    const int*   center    = (const int*)  d_in[0];
    const int*   outside   = (const int*)  d_in[1];
    const float* coocs     = (const float*)d_in[2];
    const float* weighting = (const float*)d_in[3];
    const float* cemb      = (const float*)d_in[4];
    const float* oemb      = (const float*)d_in[5];
    const float* cbias     = (const float*)d_in[6];
    const float* obias     = (const float*)d_in[7];
    float* out = (float*)d_out;

    glove_hist_kernel<<<BATCH_N / THREADS, THREADS>>>(center);
    glove_scan_kernel<<<1, NBUCKETS>>>();
    glove_scatter_kernel<<<BATCH_N / THREADS, THREADS>>>(center, outside, coocs, weighting);
    glove_main_kernel<<<BLOCKS, THREADS>>>(cemb, oemb, cbias, obias, out);
}

// round 4
// speedup vs baseline: 1.2696x; 1.2696x over previous
#include <cuda_runtime.h>
#include <cstddef>

// GloVe loss — bucketed-by-center with contention-free single-kernel scatter.
//   Launch 1 (scatter): smem hist -> bulk bucket-range reserve -> scatter
//                       {c,o,cooc,w} into fixed 512-slot buckets (pad = w==0).
//   Launch 2 (main):    walk buckets in order; center gathers are L2-local and
//                       streamed (__ldcs) so the outside table owns L2.

static constexpr int EMB           = 300;
static constexpr int NV4           = EMB / 4;       // 75 float4 per row
static constexpr int BATCH_N       = 262144;

static constexpr int BUCKET_SHIFT  = 7;
static constexpr int NB            = 1024;          // cursor table size
static constexpr int NB_USED       = 782;           // ceil(100000/128)
static constexpr int SLOT_CAP      = 512;           // >= max bucket count (~400)
static constexpr int SLOTS         = NB_USED * SLOT_CAP;   // 400384

static constexpr int STHREADS      = 512;
static constexpr int SCHUNK        = 2048;
static constexpr int SBLOCKS       = BATCH_N / SCHUNK;     // 128

static constexpr int THREADS       = 256;
static constexpr int WARPS_PER_BLK = THREADS / 32;  // 8
static constexpr int ROWS_PER_WARP = 4;
static constexpr int MBLOCKS       = SLOTS / (WARPS_PER_BLK * ROWS_PER_WARP); // 12512

// Zero-initialized at load. g_cursor/g_acc/g_done restored by last main block.
// s_recs: written slots are overwritten every replay; never-written slots stay
// zero (weight bits == 0 -> skipped), so no reset needed.
__device__ int    g_cursor[NB];
__device__ int4   s_recs[SLOTS];
__device__ double g_acc;
__device__ unsigned int g_done;

// ---- 1) fused hist + range-reserve + scatter --------------------------------
__global__ __launch_bounds__(STHREADS) void glove_scatter_kernel(
    const int*   __restrict__ center,
    const int*   __restrict__ outside,
    const float* __restrict__ coocs,
    const float* __restrict__ weighting)
{
    __shared__ int hist[NB];
    __shared__ int base[NB];
    const int tid  = threadIdx.x;
    const int idx0 = blockIdx.x * SCHUNK;

    for (int i = tid; i < NB; i += STHREADS) hist[i] = 0;
    __syncthreads();

    int c[SCHUNK / STHREADS];
    #pragma unroll
    for (int k = 0; k < SCHUNK / STHREADS; ++k) {
        c[k] = __ldg(center + idx0 + k * STHREADS + tid);
        atomicAdd(&hist[c[k] >> BUCKET_SHIFT], 1);
    }
    __syncthreads();

    // Reserve this block's range in each nonzero bucket (<=128-way contention).
    for (int b = tid; b < NB; b += STHREADS) {
        const int n = hist[b];
        base[b] = n ? atomicAdd(&g_cursor[b], n) : 0;
    }
    __syncthreads();
    for (int i = tid; i < NB; i += STHREADS) hist[i] = 0;  // reuse as cursor
    __syncthreads();

    #pragma unroll
    for (int k = 0; k < SCHUNK / STHREADS; ++k) {
        const int i = idx0 + k * STHREADS + tid;
        const int b = c[k] >> BUCKET_SHIFT;
        const int off = atomicAdd(&hist[b], 1);
        int4 rec;
        rec.x = c[k];
        rec.y = __ldg(outside + i);
        rec.z = __float_as_int(__ldg(coocs + i));
        rec.w = __float_as_int(__ldg(weighting + i));
        s_recs[b * SLOT_CAP + base[b] + off] = rec;
    }
}

// ---- 2) main gather + reduce ------------------------------------------------
__global__ __launch_bounds__(THREADS) void glove_main_kernel(
    const float* __restrict__ cemb,
    const float* __restrict__ oemb,
    const float* __restrict__ cbias,
    const float* __restrict__ obias,
    float*       __restrict__ out)
{
    const int lane  = threadIdx.x & 31;
    const int warp  = threadIdx.x >> 5;
    const int gwarp = blockIdx.x * WARPS_PER_BLK + warp;

    float wsum = 0.0f;

    #pragma unroll
    for (int r = 0; r < ROWS_PER_WARP; ++r) {
        const int slot = gwarp * ROWS_PER_WARP + r;
        const int4 rec = __ldcs(&s_recs[slot]);   // broadcast, streaming
        if (rec.w == 0) continue;                 // padding slot (uniform branch)

        const int ci = rec.x;
        const int oi = rec.y;

        const float4* __restrict__ ca = reinterpret_cast<const float4*>(cemb + (size_t)ci * EMB);
        const float4* __restrict__ ob = reinterpret_cast<const float4*>(oemb + (size_t)oi * EMB);

        // center: evict-first streaming (reuse is immediate among neighbors);
        // outside: default caching so it keeps L2 residency.
        float4 a0 = __ldcs(ca + lane);
        float4 b0 = __ldg (ob + lane);
        float4 a1 = __ldcs(ca + lane + 32);
        float4 b1 = __ldg (ob + lane + 32);
        float4 a2 = make_float4(0.f, 0.f, 0.f, 0.f);
        float4 b2 = make_float4(0.f, 0.f, 0.f, 0.f);
        if (lane < NV4 - 64) {   // lanes 0..10 cover float4 indices 64..74
            a2 = __ldcs(ca + lane + 64);
            b2 = __ldg (ob + lane + 64);
        }

        float dot = a0.x * b0.x + a0.y * b0.y + a0.z * b0.z + a0.w * b0.w;
        dot      += a1.x * b1.x + a1.y * b1.y + a1.z * b1.z + a1.w * b1.w;
        dot      += a2.x * b2.x + a2.y * b2.y + a2.z * b2.z + a2.w * b2.w;

        #pragma unroll
        for (int off = 16; off; off >>= 1)
            dot += __shfl_xor_sync(0xffffffffu, dot, off);

        if (lane == 0) {
            const float err = dot + __ldg(cbias + ci) + __ldg(obias + oi)
                            - __int_as_float(rec.z);
            wsum += __int_as_float(rec.w) * err * err;
        }
    }

    __shared__ float sh[WARPS_PER_BLK];
    if (lane == 0) sh[warp] = wsum;
    __syncthreads();

    if (threadIdx.x == 0) {
        float s = 0.0f;
        #pragma unroll
        for (int i = 0; i < WARPS_PER_BLK; ++i) s += sh[i];
        atomicAdd(&g_acc, (double)s);

        __threadfence();
        const unsigned t = atomicAdd(&g_done, 1u);
        if (t == (unsigned)(MBLOCKS - 1)) {
            const double v = atomicAdd(&g_acc, 0.0);
            out[0] = (float)v;
            g_acc  = 0.0;
            g_done = 0u;
            for (int i = 0; i < NB; ++i) g_cursor[i] = 0;  // replay-safe reset
        }
    }
}

extern "C" void kernel_launch(void* const* d_in, const int* in_sizes, int n_in,
                              void* d_out, int out_size) {
    const int*   center    = (const int*)  d_in[0];
    const int*   outside   = (const int*)  d_in[1];
    const float* coocs     = (const float*)d_in[2];
    const float* weighting = (const float*)d_in[3];
    const float* cemb      = (const float*)d_in[4];
    const float* oemb      = (const float*)d_in[5];
    const float* cbias     = (const float*)d_in[6];
    const float* obias     = (const float*)d_in[7];
    float* out = (float*)d_out;

    glove_scatter_kernel<<<SBLOCKS, STHREADS>>>(center, outside, coocs, weighting);
    glove_main_kernel<<<MBLOCKS, THREADS>>>(cemb, oemb, cbias, obias, out);
}

// round 5
// speedup vs baseline: 1.4346x; 1.1300x over previous
#include <cuda_runtime.h>
#include <cstddef>

// GloVe loss — compact counting-sort by center + software-pipelined main.
// Launches: hist -> scan -> scatter (compact, no padding) -> main (pipelined).

static constexpr int EMB           = 300;
static constexpr int NV4           = EMB / 4;       // 75 float4 per row
static constexpr int BATCH_N       = 262144;

static constexpr int BUCKET_SHIFT  = 7;
static constexpr int NB            = 1024;          // covers 100000>>7 = 782

static constexpr int STHREADS      = 512;
static constexpr int SCHUNK        = 2048;
static constexpr int SBLOCKS      = BATCH_N / SCHUNK;   // 128
static constexpr int SPT           = SCHUNK / STHREADS;  // 4

static constexpr int THREADS       = 256;
static constexpr int WARPS_PER_BLK = THREADS / 32;  // 8
static constexpr int ROWS_PER_WARP = 4;
static constexpr int MBLOCKS       = BATCH_N / (WARPS_PER_BLK * ROWS_PER_WARP); // 8192

// Replay-safe state: g_cnt zeroed by scan after reading; g_base rewritten by
// scan; s_recs fully overwritten (compact); g_acc/g_done reset by last block.
__device__ int    g_cnt[NB];
__device__ int    g_base[NB];
__device__ int4   s_recs[BATCH_N];
__device__ double g_acc;
__device__ unsigned int g_done;

// ---- 1) histogram (smem, then one global atomic per block x bucket) ---------
__global__ __launch_bounds__(STHREADS) void glove_hist_kernel(
    const int* __restrict__ center)
{
    __shared__ int h[NB];
    const int tid  = threadIdx.x;
    const int idx0 = blockIdx.x * SCHUNK;
    for (int i = tid; i < NB; i += STHREADS) h[i] = 0;
    __syncthreads();
    #pragma unroll
    for (int k = 0; k < SPT; ++k) {
        const int c = __ldg(center + idx0 + k * STHREADS + tid);
        atomicAdd(&h[c >> BUCKET_SHIFT], 1);
    }
    __syncthreads();
    for (int b = tid; b < NB; b += STHREADS)
        if (h[b]) atomicAdd(&g_cnt[b], h[b]);
}

// ---- 2) exclusive scan, re-zero counts -------------------------------------
__global__ __launch_bounds__(NB) void glove_scan_kernel()
{
    __shared__ int tmp[NB];
    const int t = threadIdx.x;
    const int v = g_cnt[t];
    g_cnt[t] = 0;                       // restore for next replay
    tmp[t] = v;
    __syncthreads();
    #pragma unroll
    for (int off = 1; off < NB; off <<= 1) {
        int u = (t >= off) ? tmp[t - off] : 0;
        __syncthreads();
        tmp[t] += u;
        __syncthreads();
    }
    g_base[t] = tmp[t] - v;             // exclusive prefix
}

// ---- 3) compact scatter (smem hist -> bulk reserve -> smem cursors) ---------
__global__ __launch_bounds__(STHREADS) void glove_scatter_kernel(
    const int*   __restrict__ center,
    const int*   __restrict__ outside,
    const float* __restrict__ coocs,
    const float* __restrict__ weighting)
{
    __shared__ int h[NB];
    __shared__ int base[NB];
    const int tid  = threadIdx.x;
    const int idx0 = blockIdx.x * SCHUNK;

    for (int i = tid; i < NB; i += STHREADS) h[i] = 0;
    __syncthreads();

    int c[SPT];
    #pragma unroll
    for (int k = 0; k < SPT; ++k) {
        c[k] = __ldg(center + idx0 + k * STHREADS + tid);
        atomicAdd(&h[c[k] >> BUCKET_SHIFT], 1);
    }
    __syncthreads();
    for (int b = tid; b < NB; b += STHREADS) {
        const int n = h[b];
        base[b] = n ? atomicAdd(&g_base[b], n) : 0;
    }
    __syncthreads();
    for (int i = tid; i < NB; i += STHREADS) h[i] = 0;   // reuse as cursor
    __syncthreads();

    #pragma unroll
    for (int k = 0; k < SPT; ++k) {
        const int i = idx0 + k * STHREADS + tid;
        const int b = c[k] >> BUCKET_SHIFT;
        const int off = atomicAdd(&h[b], 1);
        int4 rec;
        rec.x = c[k];
        rec.y = __ldg(outside + i);
        rec.z = __float_as_int(__ldg(coocs + i));
        rec.w = __float_as_int(__ldg(weighting + i));
        s_recs[base[b] + off] = rec;
    }
}

// ---- 4) pipelined main ------------------------------------------------------
struct EmbBuf {
    float4 a0, a1, a2, b0, b1, b2;
    float  cb, ob;
};

__device__ __forceinline__ void issue_embeds(
    EmbBuf& E, const int4& rec, int lane,
    const float* __restrict__ cemb, const float* __restrict__ oemb,
    const float* __restrict__ cbias, const float* __restrict__ obias)
{
    const float4* __restrict__ ca = reinterpret_cast<const float4*>(cemb + (size_t)rec.x * EMB);
    const float4* __restrict__ ob = reinterpret_cast<const float4*>(oemb + (size_t)rec.y * EMB);
    E.a0 = __ldg(ca + lane);
    E.b0 = __ldg(ob + lane);
    E.a1 = __ldg(ca + lane + 32);
    E.b1 = __ldg(ob + lane + 32);
    if (lane < NV4 - 64) {
        E.a2 = __ldg(ca + lane + 64);
        E.b2 = __ldg(ob + lane + 64);
    } else {
        E.a2 = make_float4(0.f, 0.f, 0.f, 0.f);
        E.b2 = make_float4(0.f, 0.f, 0.f, 0.f);
    }
    E.cb = __ldg(cbias + rec.x);
    E.ob = __ldg(obias + rec.y);
}

__device__ __forceinline__ float compute_row(const EmbBuf& E, const int4& rec)
{
    float dot = E.a0.x * E.b0.x + E.a0.y * E.b0.y + E.a0.z * E.b0.z + E.a0.w * E.b0.w;
    dot      += E.a1.x * E.b1.x + E.a1.y * E.b1.y + E.a1.z * E.b1.z + E.a1.w * E.b1.w;
    dot      += E.a2.x * E.b2.x + E.a2.y * E.b2.y + E.a2.z * E.b2.z + E.a2.w * E.b2.w;
    #pragma unroll
    for (int off = 16; off; off >>= 1)
        dot += __shfl_xor_sync(0xffffffffu, dot, off);
    const float err = dot + E.cb + E.ob - __int_as_float(rec.z);
    return __int_as_float(rec.w) * err * err;   // same value in every lane
}

__global__ __launch_bounds__(THREADS, 3) void glove_main_kernel(
    const float* __restrict__ cemb,
    const float* __restrict__ oemb,
    const float* __restrict__ cbias,
    const float* __restrict__ obias,
    float*       __restrict__ out)
{
    const int lane  = threadIdx.x & 31;
    const int warp  = threadIdx.x >> 5;
    const int gwarp = blockIdx.x * WARPS_PER_BLK + warp;
    const int s0    = gwarp * ROWS_PER_WARP;

    // 2-stage software pipeline: rec prefetched 1 row ahead of its embed
    // loads; embed loads issued 1 row ahead of their compute.
    int4 rec0 = __ldg(&s_recs[s0 + 0]);
    int4 rec1 = __ldg(&s_recs[s0 + 1]);

    EmbBuf E0, E1, E2, E3;
    issue_embeds(E0, rec0, lane, cemb, oemb, cbias, obias);
    int4 rec2 = __ldg(&s_recs[s0 + 2]);
    issue_embeds(E1, rec1, lane, cemb, oemb, cbias, obias);
    int4 rec3 = __ldg(&s_recs[s0 + 3]);

    float wsum = compute_row(E0, rec0);
    issue_embeds(E2, rec2, lane, cemb, oemb, cbias, obias);
    wsum += compute_row(E1, rec1);
    issue_embeds(E3, rec3, lane, cemb, oemb, cbias, obias);
    wsum += compute_row(E2, rec2);
    wsum += compute_row(E3, rec3);

    __shared__ float sh[WARPS_PER_BLK];
    if (lane == 0) sh[warp] = wsum;
    __syncthreads();

    if (threadIdx.x == 0) {
        float s = 0.0f;
        #pragma unroll
        for (int i = 0; i < WARPS_PER_BLK; ++i) s += sh[i];
        atomicAdd(&g_acc, (double)s);

        __threadfence();
        const unsigned t = atomicAdd(&g_done, 1u);
        if (t == (unsigned)(MBLOCKS - 1)) {
            const double v = atomicAdd(&g_acc, 0.0);
            out[0] = (float)v;
            g_acc  = 0.0;
            g_done = 0u;
        }
    }
}

extern "C" void kernel_launch(void* const* d_in, const int* in_sizes, int n_in,
                              void* d_out, int out_size) {
    const int*   center    = (const int*)  d_in[0];
    const int*   outside   = (const int*)  d_in[1];
    const float* coocs     = (const float*)d_in[2];
    const float* weighting = (const float*)d_in[3];
    const float* cemb      = (const float*)d_in[4];
    const float* oemb      = (const float*)d_in[5];
    const float* cbias     = (const float*)d_in[6];
    const float* obias     = (const float*)d_in[7];
    float* out = (float*)d_out;

    glove_hist_kernel<<<SBLOCKS, STHREADS>>>(center);
    glove_scan_kernel<<<1, NB>>>();
    glove_scatter_kernel<<<SBLOCKS, STHREADS>>>(center, outside, coocs, weighting);
    glove_main_kernel<<<MBLOCKS, THREADS>>>(cemb, oemb, cbias, obias, out);
}

// round 6
// speedup vs baseline: 1.5866x; 1.1059x over previous
#include <cuda_runtime.h>
#include <cstddef>

// GloVe loss — compact counting-sort by center (3 aux launches) + main gather
// tuned for occupancy: <=40 regs (launch_bounds(256,6)), 32-bit indexing,
// R1-proven 6x LDG.128 front-batched loop.

static constexpr int EMB           = 300;
static constexpr int NV4           = EMB / 4;       // 75 float4 per row
static constexpr int BATCH_N       = 262144;

static constexpr int BUCKET_SHIFT  = 7;
static constexpr int NB            = 1024;          // covers 100000>>7 = 782

static constexpr int STHREADS      = 512;
static constexpr int SCHUNK        = 2048;
static constexpr int SBLOCKS      = BATCH_N / SCHUNK;   // 128
static constexpr int SPT           = SCHUNK / STHREADS;  // 4

static constexpr int THREADS       = 256;
static constexpr int WARPS_PER_BLK = THREADS / 32;  // 8
static constexpr int ROWS_PER_WARP = 4;
static constexpr int MBLOCKS       = BATCH_N / (WARPS_PER_BLK * ROWS_PER_WARP); // 8192

// Replay-safe state: g_cnt zeroed by scan after reading; g_base fully
// rewritten by scan each launch; s_recs fully overwritten (compact);
// g_acc/g_done reset by the last main block.
__device__ int    g_cnt[NB];
__device__ int    g_base[NB];
__device__ int4   s_recs[BATCH_N];
__device__ double g_acc;
__device__ unsigned int g_done;

// ---- 1) histogram -----------------------------------------------------------
__global__ __launch_bounds__(STHREADS) void glove_hist_kernel(
    const int* __restrict__ center)
{
    __shared__ int h[NB];
    const int tid  = threadIdx.x;
    const int idx0 = blockIdx.x * SCHUNK;
    for (int i = tid; i < NB; i += STHREADS) h[i] = 0;
    __syncthreads();
    #pragma unroll
    for (int k = 0; k < SPT; ++k) {
        const int c = __ldg(center + idx0 + k * STHREADS + tid);
        atomicAdd(&h[c >> BUCKET_SHIFT], 1);
    }
    __syncthreads();
    for (int b = tid; b < NB; b += STHREADS)
        if (h[b]) atomicAdd(&g_cnt[b], h[b]);
}

// ---- 2) exclusive scan; re-zero counts for replay ---------------------------
__global__ __launch_bounds__(NB) void glove_scan_kernel()
{
    __shared__ int tmp[NB];
    const int t = threadIdx.x;
    const int v = g_cnt[t];
    g_cnt[t] = 0;
    tmp[t] = v;
    __syncthreads();
    #pragma unroll
    for (int off = 1; off < NB; off <<= 1) {
        int u = (t >= off) ? tmp[t - off] : 0;
        __syncthreads();
        tmp[t] += u;
        __syncthreads();
    }
    g_base[t] = tmp[t] - v;
}

// ---- 3) compact scatter -----------------------------------------------------
__global__ __launch_bounds__(STHREADS) void glove_scatter_kernel(
    const int*   __restrict__ center,
    const int*   __restrict__ outside,
    const float* __restrict__ coocs,
    const float* __restrict__ weighting)
{
    __shared__ int h[NB];
    __shared__ int base[NB];
    const int tid  = threadIdx.x;
    const int idx0 = blockIdx.x * SCHUNK;

    for (int i = tid; i < NB; i += STHREADS) h[i] = 0;
    __syncthreads();

    int c[SPT];
    #pragma unroll
    for (int k = 0; k < SPT; ++k) {
        c[k] = __ldg(center + idx0 + k * STHREADS + tid);
        atomicAdd(&h[c[k] >> BUCKET_SHIFT], 1);
    }
    __syncthreads();
    for (int b = tid; b < NB; b += STHREADS) {
        const int n = h[b];
        base[b] = n ? atomicAdd(&g_base[b], n) : 0;
    }
    __syncthreads();
    for (int i = tid; i < NB; i += STHREADS) h[i] = 0;   // reuse as cursors
    __syncthreads();

    #pragma unroll
    for (int k = 0; k < SPT; ++k) {
        const int i = idx0 + k * STHREADS + tid;
        const int b = c[k] >> BUCKET_SHIFT;
        const int off = atomicAdd(&h[b], 1);
        int4 rec;
        rec.x = c[k];
        rec.y = __ldg(outside + i);
        rec.z = __float_as_int(__ldg(coocs + i));
        rec.w = __float_as_int(__ldg(weighting + i));
        s_recs[base[b] + off] = rec;
    }
}

// ---- 4) main gather + reduce (occupancy-tuned) ------------------------------
__global__ __launch_bounds__(THREADS, 6) void glove_main_kernel(
    const float* __restrict__ cemb,
    const float* __restrict__ oemb,
    const float* __restrict__ cbias,
    const float* __restrict__ obias,
    float*       __restrict__ out)
{
    const int lane  = threadIdx.x & 31;
    const int warp  = threadIdx.x >> 5;
    const int gwarp = blockIdx.x * WARPS_PER_BLK + warp;

    const float4* __restrict__ cemb4 = reinterpret_cast<const float4*>(cemb);
    const float4* __restrict__ oemb4 = reinterpret_cast<const float4*>(oemb);

    float wsum = 0.0f;

    #pragma unroll
    for (int r = 0; r < ROWS_PER_WARP; ++r) {
        const int row = gwarp * ROWS_PER_WARP + r;
        const int4 rec = __ldg(&s_recs[row]);

        // 32-bit float4-element offsets: max 100000*75 + 74 < 2^23, no 64-bit math.
        const unsigned co = (unsigned)rec.x * (unsigned)NV4 + (unsigned)lane;
        const unsigned oo = (unsigned)rec.y * (unsigned)NV4 + (unsigned)lane;

        // 6 independent LDG.E.128 front-batched.
        float4 a0 = __ldg(cemb4 + co);
        float4 b0 = __ldg(oemb4 + oo);
        float4 a1 = __ldg(cemb4 + co + 32);
        float4 b1 = __ldg(oemb4 + oo + 32);
        float4 a2 = make_float4(0.f, 0.f, 0.f, 0.f);
        float4 b2 = make_float4(0.f, 0.f, 0.f, 0.f);
        if (lane < NV4 - 64) {   // lanes 0..10 cover float4 indices 64..74
            a2 = __ldg(cemb4 + co + 64);
            b2 = __ldg(oemb4 + oo + 64);
        }

        float dot = a0.x * b0.x + a0.y * b0.y + a0.z * b0.z + a0.w * b0.w;
        dot      += a1.x * b1.x + a1.y * b1.y + a1.z * b1.z + a1.w * b1.w;
        dot      += a2.x * b2.x + a2.y * b2.y + a2.z * b2.z + a2.w * b2.w;

        #pragma unroll
        for (int off = 16; off; off >>= 1)
            dot += __shfl_xor_sync(0xffffffffu, dot, off);

        if (lane == 0) {
            const float err = dot + __ldg(cbias + rec.x) + __ldg(obias + rec.y)
                            - __int_as_float(rec.z);
            wsum += __int_as_float(rec.w) * err * err;
        }
    }

    __shared__ float sh[WARPS_PER_BLK];
    if (lane == 0) sh[warp] = wsum;
    __syncthreads();

    if (threadIdx.x == 0) {
        float s = 0.0f;
        #pragma unroll
        for (int i = 0; i < WARPS_PER_BLK; ++i) s += sh[i];
        atomicAdd(&g_acc, (double)s);

        __threadfence();
        const unsigned t = atomicAdd(&g_done, 1u);
        if (t == (unsigned)(MBLOCKS - 1)) {
            const double v = atomicAdd(&g_acc, 0.0);
            out[0] = (float)v;
            g_acc  = 0.0;
            g_done = 0u;
        }
    }
}

extern "C" void kernel_launch(void* const* d_in, const int* in_sizes, int n_in,
                              void* d_out, int out_size) {
    const int*   center    = (const int*)  d_in[0];
    const int*   outside   = (const int*)  d_in[1];
    const float* coocs     = (const float*)d_in[2];
    const float* weighting = (const float*)d_in[3];
    const float* cemb      = (const float*)d_in[4];
    const float* oemb      = (const float*)d_in[5];
    const float* cbias     = (const float*)d_in[6];
    const float* obias     = (const float*)d_in[7];
    float* out = (float*)d_out;

    glove_hist_kernel<<<SBLOCKS, STHREADS>>>(center);
    glove_scan_kernel<<<1, NB>>>();
    glove_scatter_kernel<<<SBLOCKS, STHREADS>>>(center, outside, coocs, weighting);
    glove_main_kernel<<<MBLOCKS, THREADS>>>(cemb, oemb, cbias, obias, out);
}

// round 7
// speedup vs baseline: 1.7597x; 1.1091x over previous
#include <cuda_runtime.h>
#include <cstddef>

// GloVe loss — EXACT counting-sort by center (two-level: bucket by c>>7 then
// in-bucket by c&127) + main gather with register-held center-row reuse.
// Equal center indices are adjacent after the sort, so a warp reloads the
// 1.2KB center row only on index change (avg multiplicity 2.83 -> ~57% of
// center traffic eliminated).

static constexpr int EMB           = 300;
static constexpr int NV4           = EMB / 4;       // 75 float4 per row
static constexpr int BATCH_N       = 262144;

static constexpr int BUCKET_SHIFT  = 7;
static constexpr int NB            = 1024;          // covers 100000>>7 = 782
static constexpr int NB_USED       = 782;
static constexpr int SORT_CAP      = 768;           // max in-bucket records (avg 335, sd 18)

static constexpr int STHREADS      = 512;
static constexpr int SCHUNK        = 2048;
static constexpr int SBLOCKS      = BATCH_N / SCHUNK;   // 128
static constexpr int SPT           = SCHUNK / STHREADS;  // 4

static constexpr int THREADS       = 256;
static constexpr int WARPS_PER_BLK = THREADS / 32;  // 8
static constexpr int ROWS_PER_WARP = 8;
static constexpr int MBLOCKS       = BATCH_N / (WARPS_PER_BLK * ROWS_PER_WARP); // 4096

// Replay-safe: g_cnt zeroed by scan after read; g_base rewritten by scan;
// s_recs fully overwritten; g_acc/g_done reset by last main block.
__device__ int    g_cnt[NB];
__device__ int    g_base[NB];
__device__ int4   s_recs[BATCH_N];
__device__ double g_acc;
__device__ unsigned int g_done;

// ---- 1) histogram by c>>7 ---------------------------------------------------
__global__ __launch_bounds__(STHREADS) void glove_hist_kernel(
    const int* __restrict__ center)
{
    __shared__ int h[NB];
    const int tid  = threadIdx.x;
    const int idx0 = blockIdx.x * SCHUNK;
    for (int i = tid; i < NB; i += STHREADS) h[i] = 0;
    __syncthreads();
    #pragma unroll
    for (int k = 0; k < SPT; ++k) {
        const int c = __ldg(center + idx0 + k * STHREADS + tid);
        atomicAdd(&h[c >> BUCKET_SHIFT], 1);
    }
    __syncthreads();
    for (int b = tid; b < NB; b += STHREADS)
        if (h[b]) atomicAdd(&g_cnt[b], h[b]);
}

// ---- 2) exclusive scan; re-zero counts for replay ---------------------------
__global__ __launch_bounds__(NB) void glove_scan_kernel()
{
    __shared__ int tmp[NB];
    const int t = threadIdx.x;
    const int v = g_cnt[t];
    g_cnt[t] = 0;
    tmp[t] = v;
    __syncthreads();
    #pragma unroll
    for (int off = 1; off < NB; off <<= 1) {
        int u = (t >= off) ? tmp[t - off] : 0;
        __syncthreads();
        tmp[t] += u;
        __syncthreads();
    }
    g_base[t] = tmp[t] - v;
}

// ---- 3) bucketed scatter ----------------------------------------------------
// After this kernel, g_base[b] == end offset of bucket b (== start of b+1).
__global__ __launch_bounds__(STHREADS) void glove_scatter_kernel(
    const int*   __restrict__ center,
    const int*   __restrict__ outside,
    const float* __restrict__ coocs,
    const float* __restrict__ weighting)
{
    __shared__ int h[NB];
    __shared__ int base[NB];
    const int tid  = threadIdx.x;
    const int idx0 = blockIdx.x * SCHUNK;

    for (int i = tid; i < NB; i += STHREADS) h[i] = 0;
    __syncthreads();

    int c[SPT];
    #pragma unroll
    for (int k = 0; k < SPT; ++k) {
        c[k] = __ldg(center + idx0 + k * STHREADS + tid);
        atomicAdd(&h[c[k] >> BUCKET_SHIFT], 1);
    }
    __syncthreads();
    for (int b = tid; b < NB; b += STHREADS) {
        const int n = h[b];
        base[b] = n ? atomicAdd(&g_base[b], n) : 0;
    }
    __syncthreads();
    for (int i = tid; i < NB; i += STHREADS) h[i] = 0;   // reuse as cursors
    __syncthreads();

    #pragma unroll
    for (int k = 0; k < SPT; ++k) {
        const int i = idx0 + k * STHREADS + tid;
        const int b = c[k] >> BUCKET_SHIFT;
        const int off = atomicAdd(&h[b], 1);
        int4 rec;
        rec.x = c[k];
        rec.y = __ldg(outside + i);
        rec.z = __float_as_int(__ldg(coocs + i));
        rec.w = __float_as_int(__ldg(weighting + i));
        s_recs[base[b] + off] = rec;
    }
}

// ---- 3b) in-bucket counting sort by c&127 -> exact sort by center -----------
__global__ __launch_bounds__(256) void glove_sort2_kernel()
{
    __shared__ int4 buf[SORT_CAP];
    __shared__ int  cnt[128];
    __shared__ int  pos[128];
    const int b   = blockIdx.x;
    const int tid = threadIdx.x;
    const int s   = (b == 0) ? 0 : g_base[b - 1];
    const int e   = g_base[b];
    const int n   = e - s;
    if (n <= 0 || n > SORT_CAP) return;   // >CAP: skip sort (perf-only, ~never)

    if (tid < 128) cnt[tid] = 0;
    __syncthreads();
    for (int i = tid; i < n; i += 256) {
        const int4 r = s_recs[s + i];
        buf[i] = r;
        atomicAdd(&cnt[r.x & 127], 1);
    }
    __syncthreads();
    // Hillis-Steele inclusive scan over 128 counters -> exclusive in pos
    if (tid < 128) pos[tid] = cnt[tid];
    __syncthreads();
    #pragma unroll
    for (int off = 1; off < 128; off <<= 1) {
        int u = (tid < 128 && tid >= off) ? pos[tid - off] : 0;
        __syncthreads();
        if (tid < 128) pos[tid] += u;
        __syncthreads();
    }
    if (tid < 128) pos[tid] -= cnt[tid];  // exclusive prefix = cursor
    __syncthreads();
    for (int i = tid; i < n; i += 256) {
        const int4 r = buf[i];
        const int p = atomicAdd(&pos[r.x & 127], 1);
        s_recs[s + p] = r;
    }
}

// ---- 4) main gather with center-row register reuse --------------------------
__global__ __launch_bounds__(THREADS, 6) void glove_main_kernel(
    const float* __restrict__ cemb,
    const float* __restrict__ oemb,
    const float* __restrict__ cbias,
    const float* __restrict__ obias,
    float*       __restrict__ out)
{
    const int lane  = threadIdx.x & 31;
    const int warp  = threadIdx.x >> 5;
    const int gwarp = blockIdx.x * WARPS_PER_BLK + warp;

    const float4* __restrict__ cemb4 = reinterpret_cast<const float4*>(cemb);
    const float4* __restrict__ oemb4 = reinterpret_cast<const float4*>(oemb);

    float wsum = 0.0f;
    int   prev = -1;
    float4 a0, a1, a2;
    float  cb = 0.0f;
    a0 = a1 = a2 = make_float4(0.f, 0.f, 0.f, 0.f);

    #pragma unroll 1
    for (int r = 0; r < ROWS_PER_WARP; ++r) {
        const int row = gwarp * ROWS_PER_WARP + r;
        const int4 rec = __ldg(&s_recs[row]);

        const unsigned oo = (unsigned)rec.y * (unsigned)NV4 + (unsigned)lane;
        // Issue outside loads first (always needed) for MLP.
        float4 b0 = __ldg(oemb4 + oo);
        float4 b1 = __ldg(oemb4 + oo + 32);
        float4 b2 = make_float4(0.f, 0.f, 0.f, 0.f);
        if (lane < NV4 - 64) b2 = __ldg(oemb4 + oo + 64);
        const float ob = __ldg(obias + rec.y);

        if (rec.x != prev) {   // warp-uniform branch (records sorted by center)
            const unsigned co = (unsigned)rec.x * (unsigned)NV4 + (unsigned)lane;
            a0 = __ldg(cemb4 + co);
            a1 = __ldg(cemb4 + co + 32);
            a2 = make_float4(0.f, 0.f, 0.f, 0.f);
            if (lane < NV4 - 64) a2 = __ldg(cemb4 + co + 64);
            cb = __ldg(cbias + rec.x);
            prev = rec.x;
        }

        float dot = a0.x * b0.x + a0.y * b0.y + a0.z * b0.z + a0.w * b0.w;
        dot      += a1.x * b1.x + a1.y * b1.y + a1.z * b1.z + a1.w * b1.w;
        dot      += a2.x * b2.x + a2.y * b2.y + a2.z * b2.z + a2.w * b2.w;

        #pragma unroll
        for (int off = 16; off; off >>= 1)
            dot += __shfl_xor_sync(0xffffffffu, dot, off);

        if (lane == 0) {
            const float err = dot + cb + ob - __int_as_float(rec.z);
            wsum += __int_as_float(rec.w) * err * err;
        }
    }

    __shared__ float sh[WARPS_PER_BLK];
    if (lane == 0) sh[warp] = wsum;
    __syncthreads();

    if (threadIdx.x == 0) {
        float s = 0.0f;
        #pragma unroll
        for (int i = 0; i < WARPS_PER_BLK; ++i) s += sh[i];
        atomicAdd(&g_acc, (double)s);

        __threadfence();
        const unsigned t = atomicAdd(&g_done, 1u);
        if (t == (unsigned)(MBLOCKS - 1)) {
            const double v = atomicAdd(&g_acc, 0.0);
            out[0] = (float)v;
            g_acc  = 0.0;
            g_done = 0u;
        }
    }
}

extern "C" void kernel_launch(void* const* d_in, const int* in_sizes, int n_in,
                              void* d_out, int out_size) {
    const int*   center    = (const int*)  d_in[0];
    const int*   outside   = (const int*)  d_in[1];
    const float* coocs     = (const float*)d_in[2];
    const float* weighting = (const float*)d_in[3];
    const float* cemb      = (const float*)d_in[4];
    const float* oemb      = (const float*)d_in[5];
    const float* cbias     = (const float*)d_in[6];
    const float* obias     = (const float*)d_in[7];
    float* out = (float*)d_out;

    glove_hist_kernel<<<SBLOCKS, STHREADS>>>(center);
    glove_scan_kernel<<<1, NB>>>();
    glove_scatter_kernel<<<SBLOCKS, STHREADS>>>(center, outside, coocs, weighting);
    glove_sort2_kernel<<<NB_USED, 256>>>();
    glove_main_kernel<<<MBLOCKS, THREADS>>>(cemb, oemb, cbias, obias, out);
}